// round 1
// baseline (speedup 1.0000x reference)
#include <cuda_runtime.h>

// Upscale2d: 2x zero-insert upsample + 4x4 binomial FIR, reduced to
// separable 2-tap polyphase:
//   even phase: (a + 3b)/4,  odd phase: (3b + c)/4   per axis.
// x: [8,64,256,256] f32 -> y: [8,64,512,512] f32. Zero padding at borders.

#define IN_H 256
#define IN_W 256
#define OUT_W 512
#define ROWS_PER_THREAD 4

__global__ __launch_bounds__(256) void upscale2d_kernel(
    const float* __restrict__ x, float* __restrict__ y)
{
    const int n = threadIdx.x;                 // input column 0..255
    const int g = blockIdx.x;                  // row group 0..63
    const int p = blockIdx.y;                  // plane 0..511 (N*C)

    const float* xp = x + (size_t)p * IN_H * IN_W;
    float* yp = y + (size_t)p * OUT_W * OUT_W;

    const int r0 = g * ROWS_PER_THREAD;

    // horizontal pre-combines for row r: he = x[r][n-1] + 3*x[r][n],
    //                                    ho = 3*x[r][n] + x[r][n+1]
    float peH, peO;  // he/ho of previous row (rolling window)
    {
        int r = r0 - 1;
        if (r < 0) { peH = 0.f; peO = 0.f; }
        else {
            const float* row = xp + (size_t)r * IN_W;
            float c = __ldg(row + n);
            float l = (n > 0)        ? __ldg(row + n - 1) : 0.f;
            float rr = (n < IN_W - 1) ? __ldg(row + n + 1) : 0.f;
            peH = l + 3.f * c;
            peO = 3.f * c + rr;
        }
    }

    #pragma unroll
    for (int i = 0; i <= ROWS_PER_THREAD; i++) {
        const int r = r0 + i;
        float cH, cO;
        if (r >= IN_H) { cH = 0.f; cO = 0.f; }
        else {
            const float* row = xp + (size_t)r * IN_W;
            float c = __ldg(row + n);
            float l = (n > 0)        ? __ldg(row + n - 1) : 0.f;
            float rr = (n < IN_W - 1) ? __ldg(row + n + 1) : 0.f;
            cH = l + 3.f * c;
            cO = 3.f * c + rr;
        }

        // output row 2r-1 = 2(r-1)+1: (3*he[r-1] + he[r]) / 4  (then /4 for 2D)
        if (i > 0) {
            float2 v = make_float2((3.f * peH + cH) * 0.0625f,
                                   (3.f * peO + cO) * 0.0625f);
            *(float2*)(yp + (size_t)(2 * r - 1) * OUT_W + 2 * n) = v;
        }
        // output row 2r: (he[r-1] + 3*he[r]) / 4
        if (i < ROWS_PER_THREAD) {
            float2 v = make_float2((peH + 3.f * cH) * 0.0625f,
                                   (peO + 3.f * cO) * 0.0625f);
            *(float2*)(yp + (size_t)(2 * r) * OUT_W + 2 * n) = v;
        }
        peH = cH; peO = cO;
    }
}

extern "C" void kernel_launch(void* const* d_in, const int* in_sizes, int n_in,
                              void* d_out, int out_size)
{
    const float* x = (const float*)d_in[0];
    float* y = (float*)d_out;
    // planes = total elements / (256*256) = 8*64 = 512
    int planes = in_sizes[0] / (IN_H * IN_W);
    dim3 grid(IN_H / ROWS_PER_THREAD, planes);   // (64, 512)
    upscale2d_kernel<<<grid, 256>>>(x, y);
}